// round 2
// baseline (speedup 1.0000x reference)
#include <cuda_runtime.h>
#include <math.h>

// ---------------------------------------------------------------------------
// WaveletF1DModule: 2-level sym2 DWT + FNO-style truncated spectral conv.
// B=32, N=512, M=512, modes L=32. Row index everywhere: row = b*512 + m.
// Lengths: level0 signals 257, level1 signals 130.
// Weight halves: level0 = 86, level1 = 65, D = 132.
// ---------------------------------------------------------------------------

#define RTOT 16384            // 32 * 512 rows
#define N1 257
#define N2 130

// ---- scratch (device globals; allocation-free) ----
__device__ float g_lo1[RTOT * N1];
__device__ float g_hi1[RTOT * N1];
__device__ float g_lo2[RTOT * N2];
__device__ float g_hi2[RTOT * N2];
__device__ float g_xf[4][RTOT * 64];     // 0=lo1,1=hi1,2=lo2,3=hi2 (re[32]|im[32])
__device__ float g_spec[4][RTOT * 64];   // 0=Ud0,1=Us1,2=Ud1,3=S2 (a_k-scaled)
__device__ float g_ud0[RTOT * N1];
__device__ float g_us1[RTOT * N1];
__device__ float g_ud1[RTOT * N2];
__device__ float g_s2 [RTOT * N2];
__device__ float g_y258[RTOT * 258];
__device__ float g_y512[RTOT * 512];
__device__ float g_Bf257[N1 * 64];
__device__ float g_Bi257[64 * N1];
__device__ float g_Bf130[N2 * 64];
__device__ float g_Bi130[64 * N2];
__device__ float g_W[6 * 512 * 2048];    // [w][m][ri(0/1)*1024 + j*32 + k]

// sym2 filters (conv form): g = DEC_LO reversed = REC_LO ; h = DEC_HI reversed = REC_HI
#define G0 0.48296291314469025f
#define G1 0.836516303737469f
#define G2 0.22414386804185735f
#define G3 (-0.12940952255092145f)
#define H0 (-0.12940952255092145f)
#define H1 (-0.22414386804185735f)
#define H2 0.836516303737469f
#define H3 (-0.48296291314469025f)

// ---------------------------------------------------------------------------
__global__ void prep_basis() {
    int idx = blockIdx.x * blockDim.x + threadIdx.x;
    const double TWO_PI = 6.283185307179586476925286766559;
    if (idx < N1 * 64) {
        int t = idx / 64, c = idx % 64, k = c & 31;
        double th = TWO_PI * (double)(k * t) / 257.0;
        float v = (c < 32) ? (float)cos(th) : (float)(-sin(th));
        g_Bf257[t * 64 + c] = v;
        g_Bi257[c * N1 + t] = v;
    }
    int idx2 = idx - N1 * 64;
    if (idx2 >= 0 && idx2 < N2 * 64) {
        int t = idx2 / 64, c = idx2 % 64, k = c & 31;
        double th = TWO_PI * (double)(k * t) / 130.0;
        float v = (c < 32) ? (float)cos(th) : (float)(-sin(th));
        g_Bf130[t * 64 + c] = v;
        g_Bi130[c * N2 + t] = v;
    }
}

// ---------------------------------------------------------------------------
// Weight halves: level0 arrays are (512,86,86), level1 are (512,65,65),
// D is (512,132,132). Only the top-left 32x32 block of each is used.
__global__ void pack_weights(const float* __restrict__ l0k0_r, const float* __restrict__ l0k0_i,
                             const float* __restrict__ l0k1_r, const float* __restrict__ l0k1_i,
                             const float* __restrict__ l0k2_r, const float* __restrict__ l0k2_i,
                             const float* __restrict__ l1k0_r, const float* __restrict__ l1k0_i,
                             const float* __restrict__ l1k1_r, const float* __restrict__ l1k1_i,
                             const float* __restrict__ l1k2_r, const float* __restrict__ l1k2_i,
                             const float* __restrict__ D_r,    const float* __restrict__ D_i) {
    int idx = blockIdx.x * blockDim.x + threadIdx.x;
    if (idx >= 512 * 1024) return;
    int m = idx >> 10, j = (idx >> 5) & 31, k = idx & 31;
    int dst = m * 2048 + j * 32 + k;        // ri=0; +1024 for ri=1
    int s86  = (m * 86 + j) * 86 + k;
    int s65  = (m * 65 + j) * 65 + k;
    int s132 = (m * 132 + j) * 132 + k;
    g_W[0 * 512 * 2048 + dst]        = l0k0_r[s86];
    g_W[0 * 512 * 2048 + dst + 1024] = l0k0_i[s86];
    g_W[1 * 512 * 2048 + dst]        = l0k1_r[s86];
    g_W[1 * 512 * 2048 + dst + 1024] = l0k1_i[s86];
    g_W[2 * 512 * 2048 + dst]        = l0k2_r[s86];
    g_W[2 * 512 * 2048 + dst + 1024] = l0k2_i[s86];
    g_W[3 * 512 * 2048 + dst]        = l1k0_r[s65];
    g_W[3 * 512 * 2048 + dst + 1024] = l1k0_i[s65];
    g_W[4 * 512 * 2048 + dst]        = l1k1_r[s65];
    g_W[4 * 512 * 2048 + dst + 1024] = l1k1_i[s65];
    g_W[5 * 512 * 2048 + dst]        = l1k2_r[s65] + D_r[s132];
    g_W[5 * 512 * 2048 + dst + 1024] = l1k2_i[s65] + D_i[s132];
}

// ---------------------------------------------------------------------------
// dwt level 0, fused with (n,m) transpose. x: (b,n,m). out rows = b*512+m.
__global__ void dwt0_kernel(const float* __restrict__ x) {
    __shared__ float sx[66][33];
    int m0 = blockIdx.x * 32, t0 = blockIdx.y * 32, b = blockIdx.z;
    int tid = threadIdx.y * 32 + threadIdx.x;
    int nbase = 2 * t0 - 2;
    for (int i = tid; i < 66 * 32; i += 256) {
        int r = i >> 5, c = i & 31;
        int n = nbase + r;
        if (n < 0) n = -n;
        if (n > 511) n = 1022 - n;
        sx[r][c] = x[(b * 512 + n) * 512 + m0 + c];
    }
    __syncthreads();
    int tt = threadIdx.x;
    int t = t0 + tt;
    if (t < N1) {
        #pragma unroll
        for (int q = 0; q < 4; q++) {
            int mm = threadIdx.y + 8 * q;
            float v0 = sx[2 * tt][mm], v1 = sx[2 * tt + 1][mm];
            float v2 = sx[2 * tt + 2][mm], v3 = sx[2 * tt + 3][mm];
            int row = b * 512 + m0 + mm;
            g_lo1[row * N1 + t] = G0 * v0 + G1 * v1 + G2 * v2 + G3 * v3;
            g_hi1[row * N1 + t] = H0 * v0 + H1 * v1 + H2 * v2 + H3 * v3;
        }
    }
}

// ---------------------------------------------------------------------------
__global__ void dwt1_kernel() {
    __shared__ float s[N1];
    int row = blockIdx.x;
    for (int i = threadIdx.x; i < N1; i += blockDim.x) s[i] = g_lo1[row * N1 + i];
    __syncthreads();
    for (int t = threadIdx.x; t < N2; t += blockDim.x) {
        int n = 2 * t - 2;
        float v[4];
        #pragma unroll
        for (int k = 0; k < 4; k++) {
            int nn = n + k;
            if (nn < 0) nn = -nn;
            if (nn > 256) nn = 512 - nn;
            v[k] = s[nn];
        }
        g_lo2[row * N2 + t] = G0 * v[0] + G1 * v[1] + G2 * v[2] + G3 * v[3];
        g_hi2[row * N2 + t] = H0 * v[0] + H1 * v[1] + H2 * v[2] + H3 * v[3];
    }
}

// ---------------------------------------------------------------------------
// Generic tiled SGEMM over fixed device arrays.
// MODE 0: fwd DFT 257  (A rows x 257) @ (257 x 64)
// MODE 1: fwd DFT 130
// MODE 2: inv DFT 257  (A rows x 64) @ (64 x 257)
// MODE 3: inv DFT 130
template <int MODE>
__global__ void sgemm_kernel() {
    constexpr int BM = 64, BN = 64, BK = 32, TM = 4, TN = 4;
    constexpr int K  = (MODE == 0) ? N1 : (MODE == 1) ? N2 : 64;
    constexpr int NC = (MODE == 2) ? N1 : (MODE == 3) ? N2 : 64;

    const float* A; const float* Bm; float* C;
    if (MODE == 0)      { A = blockIdx.z ? g_hi1 : g_lo1;       Bm = g_Bf257; C = blockIdx.z ? g_xf[1] : g_xf[0]; }
    else if (MODE == 1) { A = blockIdx.z ? g_hi2 : g_lo2;       Bm = g_Bf130; C = blockIdx.z ? g_xf[3] : g_xf[2]; }
    else if (MODE == 2) { A = blockIdx.z ? g_spec[1] : g_spec[0]; Bm = g_Bi257; C = blockIdx.z ? g_us1 : g_ud0; }
    else                { A = blockIdx.z ? g_spec[3] : g_spec[2]; Bm = g_Bi130; C = blockIdx.z ? g_s2  : g_ud1; }

    __shared__ float As[BM][BK + 1];
    __shared__ float Bs[BK][BN];
    int row0 = blockIdx.y * BM;
    int n0   = blockIdx.x * BN;
    int tid  = threadIdx.x;
    int tx   = tid % (BN / TN);   // 16
    int ty   = tid / (BN / TN);   // 16

    float acc[TM][TN] = {};
    for (int k0 = 0; k0 < K; k0 += BK) {
        for (int i = tid; i < BM * BK; i += 256) {
            int r = i / BK, c = i % BK;
            As[r][c] = (k0 + c < K) ? A[(row0 + r) * K + k0 + c] : 0.f;
        }
        for (int i = tid; i < BK * BN; i += 256) {
            int r = i / BN, c = i % BN;
            Bs[r][c] = (k0 + r < K && n0 + c < NC) ? Bm[(k0 + r) * NC + n0 + c] : 0.f;
        }
        __syncthreads();
        #pragma unroll
        for (int k = 0; k < BK; k++) {
            float a[TM];
            #pragma unroll
            for (int i = 0; i < TM; i++) a[i] = As[ty * TM + i][k];
            float4 b4 = *reinterpret_cast<const float4*>(&Bs[k][tx * TN]);
            float b[TN] = {b4.x, b4.y, b4.z, b4.w};
            #pragma unroll
            for (int i = 0; i < TM; i++)
                #pragma unroll
                for (int j = 0; j < TN; j++)
                    acc[i][j] += a[i] * b[j];
        }
        __syncthreads();
    }
    #pragma unroll
    for (int i = 0; i < TM; i++)
        #pragma unroll
        for (int j = 0; j < TN; j++) {
            int n = n0 + tx * TN + j;
            if (n < NC) C[(row0 + ty * TM + i) * NC + n] = acc[i][j];
        }
}

// ---------------------------------------------------------------------------
struct MixAcc { float r00, r01, r10, r11, i00, i01, i10, i11; };

__device__ __forceinline__ void mix_zero(MixAcc& a) {
    a.r00 = a.r01 = a.r10 = a.r11 = 0.f;
    a.i00 = a.i01 = a.i10 = a.i11 = 0.f;
}

__device__ __forceinline__ void mix_pass(const float* __restrict__ sx,
                                         const float* __restrict__ sw,
                                         int b0, int k0, MixAcc& a) {
    #pragma unroll
    for (int j = 0; j < 32; j++) {
        float xr0 = sx[b0 * 64 + j],        xi0 = sx[b0 * 64 + 32 + j];
        float xr1 = sx[(b0 + 1) * 64 + j],  xi1 = sx[(b0 + 1) * 64 + 32 + j];
        float wr0 = sw[j * 32 + k0],        wr1 = sw[j * 32 + k0 + 1];
        float wi0 = sw[1024 + j * 32 + k0], wi1 = sw[1024 + j * 32 + k0 + 1];
        a.r00 += xr0 * wr0 - xi0 * wi0;  a.i00 += xr0 * wi0 + xi0 * wr0;
        a.r01 += xr0 * wr1 - xi0 * wi1;  a.i01 += xr0 * wi1 + xi0 * wr1;
        a.r10 += xr1 * wr0 - xi1 * wi0;  a.i10 += xr1 * wi0 + xi1 * wr0;
        a.r11 += xr1 * wr1 - xi1 * wi1;  a.i11 += xr1 * wi1 + xi1 * wr1;
    }
}

__device__ __forceinline__ void mix_store(float* __restrict__ dst, int m, int b0, int k0,
                                          const MixAcc& a, float invN) {
    float a0 = (k0 == 0 ? 1.f : 2.f) * invN;
    float a1 = 2.f * invN;
    int base0 = ((b0) * 512 + m) * 64 + k0;
    int base1 = ((b0 + 1) * 512 + m) * 64 + k0;
    dst[base0]      = a.r00 * a0;  dst[base0 + 1]  = a.r01 * a1;
    dst[base0 + 32] = a.i00 * a0;  dst[base0 + 33] = a.i01 * a1;
    dst[base1]      = a.r10 * a0;  dst[base1 + 1]  = a.r11 * a1;
    dst[base1 + 32] = a.i10 * a0;  dst[base1 + 33] = a.i11 * a1;
}

__global__ void mix_kernel() {
    __shared__ float sxf[4][2048];
    __shared__ float sW[2048];
    int m = blockIdx.x, tid = threadIdx.x;
    for (int s = 0; s < 4; s++)
        for (int i = tid; i < 2048; i += 256) {
            int b = i >> 6, c = i & 63;
            sxf[s][i] = g_xf[s][(b * 512 + m) * 64 + c];
        }
    int b0 = (tid >> 4) * 2;
    int k0 = (tid & 15) * 2;

    MixAcc a;
    // Spec0 = Ud0 spectrum: hi1 @ W0 + lo1 @ W1, scaled by a_k/257
    mix_zero(a);
    __syncthreads();
    for (int i = tid; i < 2048; i += 256) sW[i] = g_W[0 * 512 * 2048 + m * 2048 + i];
    __syncthreads();
    mix_pass(sxf[1], sW, b0, k0, a);
    __syncthreads();
    for (int i = tid; i < 2048; i += 256) sW[i] = g_W[1 * 512 * 2048 + m * 2048 + i];
    __syncthreads();
    mix_pass(sxf[0], sW, b0, k0, a);
    mix_store(g_spec[0], m, b0, k0, a, 1.0f / 257.0f);

    // Spec1 = Us1 spectrum: lo1 @ W2
    mix_zero(a);
    __syncthreads();
    for (int i = tid; i < 2048; i += 256) sW[i] = g_W[2 * 512 * 2048 + m * 2048 + i];
    __syncthreads();
    mix_pass(sxf[0], sW, b0, k0, a);
    mix_store(g_spec[1], m, b0, k0, a, 1.0f / 257.0f);

    // Spec2 = Ud1 spectrum: hi2 @ W3 + lo2 @ W4
    mix_zero(a);
    __syncthreads();
    for (int i = tid; i < 2048; i += 256) sW[i] = g_W[3 * 512 * 2048 + m * 2048 + i];
    __syncthreads();
    mix_pass(sxf[3], sW, b0, k0, a);
    __syncthreads();
    for (int i = tid; i < 2048; i += 256) sW[i] = g_W[4 * 512 * 2048 + m * 2048 + i];
    __syncthreads();
    mix_pass(sxf[2], sW, b0, k0, a);
    mix_store(g_spec[2], m, b0, k0, a, 1.0f / 130.0f);

    // Spec3 = (Us2 + xD) spectrum: lo2 @ (W_l1k2 + W_D)
    mix_zero(a);
    __syncthreads();
    for (int i = tid; i < 2048; i += 256) sW[i] = g_W[5 * 512 * 2048 + m * 2048 + i];
    __syncthreads();
    mix_pass(sxf[2], sW, b0, k0, a);
    mix_store(g_spec[3], m, b0, k0, a, 1.0f / 130.0f);
}

// ---------------------------------------------------------------------------
__global__ void idwt1_kernel() {
    __shared__ float slo[N2], shi[N2];
    int row = blockIdx.x;
    for (int i = threadIdx.x; i < N2; i += blockDim.x) {
        slo[i] = g_s2[row * N2 + i];
        shi[i] = g_ud1[row * N2 + i];
    }
    __syncthreads();
    for (int n = threadIdx.x; n < 258; n += blockDim.x) {
        float v;
        if (n & 1) {
            int i0 = (n - 1) >> 1, i1 = (n + 1) >> 1;
            v = slo[i0] * G3 + shi[i0] * H3 + slo[i1] * G1 + shi[i1] * H1;
        } else {
            int i0 = n >> 1, i1 = i0 + 1;
            v = slo[i0] * G2 + shi[i0] * H2 + slo[i1] * G0 + shi[i1] * H0;
        }
        g_y258[row * 258 + n] = v;
    }
}

__global__ void idwt0_kernel() {
    __shared__ float slo[N1], shi[N1];
    int row = blockIdx.x;
    for (int i = threadIdx.x; i < N1; i += blockDim.x) {
        slo[i] = g_y258[row * 258 + i] + g_us1[row * N1 + i];
        shi[i] = g_ud0[row * N1 + i];
    }
    __syncthreads();
    for (int n = threadIdx.x; n < 512; n += blockDim.x) {
        float v;
        if (n & 1) {
            int i0 = (n - 1) >> 1, i1 = (n + 1) >> 1;
            v = slo[i0] * G3 + shi[i0] * H3 + slo[i1] * G1 + shi[i1] * H1;
        } else {
            int i0 = n >> 1, i1 = i0 + 1;
            v = slo[i0] * G2 + shi[i0] * H2 + slo[i1] * G0 + shi[i1] * H0;
        }
        g_y512[row * 512 + n] = v;
    }
}

// ---------------------------------------------------------------------------
__global__ void transpose_kernel(float* __restrict__ out) {
    __shared__ float tile[32][33];
    int m0 = blockIdx.x * 32, n0 = blockIdx.y * 32, b = blockIdx.z;
    int tx = threadIdx.x, ty = threadIdx.y;
    #pragma unroll
    for (int q = 0; q < 4; q++) {
        int mm = ty + 8 * q;
        tile[mm][tx] = g_y512[(b * 512 + m0 + mm) * 512 + n0 + tx];
    }
    __syncthreads();
    #pragma unroll
    for (int q = 0; q < 4; q++) {
        int nn = ty + 8 * q;
        out[(b * 512 + n0 + nn) * 512 + m0 + tx] = tile[tx][nn];
    }
}

// ---------------------------------------------------------------------------
extern "C" void kernel_launch(void* const* d_in, const int* in_sizes, int n_in,
                              void* d_out, int out_size) {
    (void)in_sizes; (void)n_in; (void)out_size;
    const float* x = (const float*)d_in[0];

    prep_basis<<<(N1 * 64 + N2 * 64 + 255) / 256, 256>>>();
    pack_weights<<<2048, 256>>>(
        (const float*)d_in[1],  (const float*)d_in[2],
        (const float*)d_in[3],  (const float*)d_in[4],
        (const float*)d_in[5],  (const float*)d_in[6],
        (const float*)d_in[7],  (const float*)d_in[8],
        (const float*)d_in[9],  (const float*)d_in[10],
        (const float*)d_in[11], (const float*)d_in[12],
        (const float*)d_in[13], (const float*)d_in[14]);

    dwt0_kernel<<<dim3(16, 9, 32), dim3(32, 8)>>>(x);
    dwt1_kernel<<<RTOT, 128>>>();

    sgemm_kernel<0><<<dim3(1, 256, 2), 256>>>();   // fwd DFT len 257 (lo1, hi1)
    sgemm_kernel<1><<<dim3(1, 256, 2), 256>>>();   // fwd DFT len 130 (lo2, hi2)

    mix_kernel<<<512, 256>>>();

    sgemm_kernel<2><<<dim3(5, 256, 2), 256>>>();   // inv DFT -> Ud0, Us1
    sgemm_kernel<3><<<dim3(3, 256, 2), 256>>>();   // inv DFT -> Ud1, S2

    idwt1_kernel<<<RTOT, 256>>>();
    idwt0_kernel<<<RTOT, 256>>>();
    transpose_kernel<<<dim3(16, 16, 32), dim3(32, 8)>>>((float*)d_out);
}

// round 3
// speedup vs baseline: 1.1935x; 1.1935x over previous
#include <cuda_runtime.h>
#include <math.h>

// ---------------------------------------------------------------------------
// WaveletF1DModule: 2-level sym2 DWT + truncated-DFT spectral conv (32 modes).
// B=32, N=512, M=512. row = b*512 + m. Signal lens: 257 (L0), 130 (L1).
// Padded strides: lo1/hi1 288, lo2/hi2 160, ud0/us1 320, ud1/s2 192.
// ---------------------------------------------------------------------------

#define RTOT 16384
#define N1 257
#define N2 130
#define N1PF 288   // fwd stride (lo1/hi1), 9 k-tiles of 32
#define N2PF 160   // fwd stride (lo2/hi2), 5 k-tiles
#define N1PI 320   // inv out stride (ud0/us1), 5 n-tiles of 64
#define N2PI 192   // inv out stride (ud1/s2), 3 n-tiles

__device__ float g_lo1[RTOT * N1PF];
__device__ float g_hi1[RTOT * N1PF];
__device__ float g_lo2[RTOT * N2PF];
__device__ float g_hi2[RTOT * N2PF];
__device__ float g_xf[4][RTOT * 64];     // 0=lo1,1=hi1,2=lo2,3=hi2 (re[32]|im[32])
__device__ float g_spec[4][RTOT * 64];   // 0=Ud0,1=Us1,2=Ud1,3=S2 (a_k-scaled)
__device__ float g_ud0[RTOT * N1PI];
__device__ float g_us1[RTOT * N1PI];
__device__ float g_ud1[RTOT * N2PI];
__device__ float g_s2 [RTOT * N2PI];
__device__ float g_Bf257[N1PF * 64];     // rows >=257 zero
__device__ float g_Bi257[64 * N1PI];     // cols >=257 zero
__device__ float g_Bf130[N2PF * 64];     // rows >=130 zero
__device__ float g_Bi130[64 * N2PI];     // cols >=130 zero
__device__ float g_W[6 * 512 * 2048];    // [w][m][ri*1024 + j*32 + k]

#define G0 0.48296291314469025f
#define G1 0.836516303737469f
#define G2 0.22414386804185735f
#define G3 (-0.12940952255092145f)
#define H0 (-0.12940952255092145f)
#define H1 (-0.22414386804185735f)
#define H2 0.836516303737469f
#define H3 (-0.48296291314469025f)

// ---------------------------------------------------------------------------
__global__ void prep_basis() {
    int idx = blockIdx.x * blockDim.x + threadIdx.x;
    const double TWO_PI = 6.283185307179586476925286766559;
    if (idx < N1 * 64) {
        int t = idx / 64, c = idx % 64, k = c & 31;
        double th = TWO_PI * (double)(k * t) / 257.0;
        float v = (c < 32) ? (float)cos(th) : (float)(-sin(th));
        g_Bf257[t * 64 + c] = v;
        g_Bi257[c * N1PI + t] = v;
    }
    int idx2 = idx - N1 * 64;
    if (idx2 >= 0 && idx2 < N2 * 64) {
        int t = idx2 / 64, c = idx2 % 64, k = c & 31;
        double th = TWO_PI * (double)(k * t) / 130.0;
        float v = (c < 32) ? (float)cos(th) : (float)(-sin(th));
        g_Bf130[t * 64 + c] = v;
        g_Bi130[c * N2PI + t] = v;
    }
}

// ---------------------------------------------------------------------------
// Weight halves: level0 (512,86,86), level1 (512,65,65), D (512,132,132).
__global__ void pack_weights(const float* __restrict__ l0k0_r, const float* __restrict__ l0k0_i,
                             const float* __restrict__ l0k1_r, const float* __restrict__ l0k1_i,
                             const float* __restrict__ l0k2_r, const float* __restrict__ l0k2_i,
                             const float* __restrict__ l1k0_r, const float* __restrict__ l1k0_i,
                             const float* __restrict__ l1k1_r, const float* __restrict__ l1k1_i,
                             const float* __restrict__ l1k2_r, const float* __restrict__ l1k2_i,
                             const float* __restrict__ D_r,    const float* __restrict__ D_i) {
    int idx = blockIdx.x * blockDim.x + threadIdx.x;
    if (idx >= 512 * 1024) return;
    int m = idx >> 10, j = (idx >> 5) & 31, k = idx & 31;
    int dst = m * 2048 + j * 32 + k;
    int s86  = (m * 86 + j) * 86 + k;
    int s65  = (m * 65 + j) * 65 + k;
    int s132 = (m * 132 + j) * 132 + k;
    g_W[0 * 512 * 2048 + dst]        = l0k0_r[s86];
    g_W[0 * 512 * 2048 + dst + 1024] = l0k0_i[s86];
    g_W[1 * 512 * 2048 + dst]        = l0k1_r[s86];
    g_W[1 * 512 * 2048 + dst + 1024] = l0k1_i[s86];
    g_W[2 * 512 * 2048 + dst]        = l0k2_r[s86];
    g_W[2 * 512 * 2048 + dst + 1024] = l0k2_i[s86];
    g_W[3 * 512 * 2048 + dst]        = l1k0_r[s65];
    g_W[3 * 512 * 2048 + dst + 1024] = l1k0_i[s65];
    g_W[4 * 512 * 2048 + dst]        = l1k1_r[s65];
    g_W[4 * 512 * 2048 + dst + 1024] = l1k1_i[s65];
    g_W[5 * 512 * 2048 + dst]        = l1k2_r[s65] + D_r[s132];
    g_W[5 * 512 * 2048 + dst + 1024] = l1k2_i[s65] + D_i[s132];
}

// ---------------------------------------------------------------------------
// Fused dwt level0 + level1. Block = (32 m's, one b). Dynamic smem:
//   sx[512][33] (x tile, transposed)  then reused for lo2/hi2 staging
//   sb[257][33] (hi then lo staging)
__global__ __launch_bounds__(256) void dwt_fused(const float* __restrict__ x) {
    extern __shared__ float dyn[];
    float* sx = dyn;                // 512*33
    float* sb = dyn + 512 * 33;     // 257*33
    int m0 = blockIdx.x * 32, b = blockIdx.y;
    int tid = threadIdx.x, lane = tid & 31, wid = tid >> 5;

    for (int i = tid; i < 512 * 32; i += 256) {
        int n = i >> 5, c = i & 31;
        sx[n * 33 + c] = x[(b * 512 + n) * 512 + m0 + c];
    }
    __syncthreads();
    // hi1 into sb
    for (int i = tid; i < 257 * 32; i += 256) {
        int t = i >> 5, c = i & 31, n = 2 * t - 2;
        float v[4];
        #pragma unroll
        for (int k = 0; k < 4; k++) {
            int nn = n + k; nn = nn < 0 ? -nn : (nn > 511 ? 1022 - nn : nn);
            v[k] = sx[nn * 33 + c];
        }
        sb[t * 33 + c] = H0 * v[0] + H1 * v[1] + H2 * v[2] + H3 * v[3];
    }
    __syncthreads();
    for (int c = wid; c < 32; c += 8) {
        int row = b * 512 + m0 + c;
        for (int t = lane; t < 257; t += 32) g_hi1[row * N1PF + t] = sb[t * 33 + c];
    }
    __syncthreads();
    // lo1 into sb
    for (int i = tid; i < 257 * 32; i += 256) {
        int t = i >> 5, c = i & 31, n = 2 * t - 2;
        float v[4];
        #pragma unroll
        for (int k = 0; k < 4; k++) {
            int nn = n + k; nn = nn < 0 ? -nn : (nn > 511 ? 1022 - nn : nn);
            v[k] = sx[nn * 33 + c];
        }
        sb[t * 33 + c] = G0 * v[0] + G1 * v[1] + G2 * v[2] + G3 * v[3];
    }
    __syncthreads();
    // flush lo1 + compute level1 from sb into sx region
    float* s2lo = sx;
    float* s2hi = sx + 130 * 33;
    for (int c = wid; c < 32; c += 8) {
        int row = b * 512 + m0 + c;
        for (int t = lane; t < 257; t += 32) g_lo1[row * N1PF + t] = sb[t * 33 + c];
    }
    for (int i = tid; i < 130 * 32; i += 256) {
        int t = i >> 5, c = i & 31, n = 2 * t - 2;
        float v[4];
        #pragma unroll
        for (int k = 0; k < 4; k++) {
            int nn = n + k; nn = nn < 0 ? -nn : (nn > 256 ? 512 - nn : nn);
            v[k] = sb[nn * 33 + c];
        }
        s2lo[t * 33 + c] = G0 * v[0] + G1 * v[1] + G2 * v[2] + G3 * v[3];
        s2hi[t * 33 + c] = H0 * v[0] + H1 * v[1] + H2 * v[2] + H3 * v[3];
    }
    __syncthreads();
    for (int c = wid; c < 32; c += 8) {
        int row = b * 512 + m0 + c;
        for (int t = lane; t < 130; t += 32) {
            g_lo2[row * N2PF + t] = s2lo[t * 33 + c];
            g_hi2[row * N2PF + t] = s2hi[t * 33 + c];
        }
    }
}

// ---------------------------------------------------------------------------
// Forward truncated DFT: C[row][64] = A[row][0..K) @ Bf.  Merged launch:
//   z=0: lo1, z=1: hi1 (KP=288, 9 k-tiles) ; z=2: lo2, z=3: hi2 (KP=160, 5)
__global__ __launch_bounds__(256) void fwd_gemm() {
    int z = blockIdx.z;
    const float* A; const float* Bf; float* C; int KP, KIT;
    if (z == 0)      { A = g_lo1; Bf = g_Bf257; C = &g_xf[0][0]; KP = N1PF; KIT = 9; }
    else if (z == 1) { A = g_hi1; Bf = g_Bf257; C = &g_xf[1][0]; KP = N1PF; KIT = 9; }
    else if (z == 2) { A = g_lo2; Bf = g_Bf130; C = &g_xf[2][0]; KP = N2PF; KIT = 5; }
    else             { A = g_hi2; Bf = g_Bf130; C = &g_xf[3][0]; KP = N2PF; KIT = 5; }

    __shared__ float As[32 * 132];
    __shared__ float Bs[32 * 64];
    int row0 = blockIdx.y * 128;
    int tid = threadIdx.x, tx = tid & 15, ty = tid >> 4;
    float acc[8][4] = {};

    for (int k0 = 0; k0 < KIT * 32; k0 += 32) {
        #pragma unroll
        for (int it = 0; it < 4; it++) {
            int lin = it * 256 + tid, r = lin >> 3, kq = lin & 7;
            float4 v = *(const float4*)&A[(row0 + r) * KP + k0 + kq * 4];
            As[(kq * 4 + 0) * 132 + r] = v.x;
            As[(kq * 4 + 1) * 132 + r] = v.y;
            As[(kq * 4 + 2) * 132 + r] = v.z;
            As[(kq * 4 + 3) * 132 + r] = v.w;
        }
        #pragma unroll
        for (int it = 0; it < 2; it++) {
            int lin = it * 256 + tid, kb = lin >> 4, cq = lin & 15;
            *(float4*)&Bs[kb * 64 + cq * 4] = *(const float4*)&Bf[(k0 + kb) * 64 + cq * 4];
        }
        __syncthreads();
        #pragma unroll
        for (int k = 0; k < 32; k++) {
            float4 a0 = *(const float4*)&As[k * 132 + ty * 8];
            float4 a1 = *(const float4*)&As[k * 132 + ty * 8 + 4];
            float4 bv = *(const float4*)&Bs[k * 64 + tx * 4];
            float a[8] = {a0.x, a0.y, a0.z, a0.w, a1.x, a1.y, a1.z, a1.w};
            float bb[4] = {bv.x, bv.y, bv.z, bv.w};
            #pragma unroll
            for (int i = 0; i < 8; i++)
                #pragma unroll
                for (int j = 0; j < 4; j++)
                    acc[i][j] += a[i] * bb[j];
        }
        __syncthreads();
    }
    #pragma unroll
    for (int i = 0; i < 8; i++) {
        float4 v = make_float4(acc[i][0], acc[i][1], acc[i][2], acc[i][3]);
        *(float4*)&C[(row0 + ty * 8 + i) * 64 + tx * 4] = v;
    }
}

// ---------------------------------------------------------------------------
// Inverse truncated DFT: C[row][NCP] = spec[row][0..64) @ Bi.  Merged launch:
//   x<5: Bi257/NCP=320 (z=0: spec0->ud0, z=1: spec1->us1)
//   x>=5: Bi130/NCP=192 (z=0: spec2->ud1, z=1: spec3->s2)
__global__ __launch_bounds__(256) void inv_gemm() {
    int xb = blockIdx.x, z = blockIdx.z;
    const float* A; const float* Bi; float* C; int NCP, n0;
    if (xb < 5) { A = z ? &g_spec[1][0] : &g_spec[0][0]; Bi = g_Bi257;
                  C = z ? g_us1 : g_ud0; NCP = N1PI; n0 = xb * 64; }
    else        { A = z ? &g_spec[3][0] : &g_spec[2][0]; Bi = g_Bi130;
                  C = z ? g_s2 : g_ud1; NCP = N2PI; n0 = (xb - 5) * 64; }

    __shared__ float As[32 * 132];
    __shared__ float Bs[32 * 64];
    int row0 = blockIdx.y * 128;
    int tid = threadIdx.x, tx = tid & 15, ty = tid >> 4;
    float acc[8][4] = {};

    for (int k0 = 0; k0 < 64; k0 += 32) {
        #pragma unroll
        for (int it = 0; it < 4; it++) {
            int lin = it * 256 + tid, r = lin >> 3, kq = lin & 7;
            float4 v = *(const float4*)&A[(row0 + r) * 64 + k0 + kq * 4];
            As[(kq * 4 + 0) * 132 + r] = v.x;
            As[(kq * 4 + 1) * 132 + r] = v.y;
            As[(kq * 4 + 2) * 132 + r] = v.z;
            As[(kq * 4 + 3) * 132 + r] = v.w;
        }
        #pragma unroll
        for (int it = 0; it < 2; it++) {
            int lin = it * 256 + tid, kb = lin >> 4, cq = lin & 15;
            *(float4*)&Bs[kb * 64 + cq * 4] = *(const float4*)&Bi[(k0 + kb) * NCP + n0 + cq * 4];
        }
        __syncthreads();
        #pragma unroll
        for (int k = 0; k < 32; k++) {
            float4 a0 = *(const float4*)&As[k * 132 + ty * 8];
            float4 a1 = *(const float4*)&As[k * 132 + ty * 8 + 4];
            float4 bv = *(const float4*)&Bs[k * 64 + tx * 4];
            float a[8] = {a0.x, a0.y, a0.z, a0.w, a1.x, a1.y, a1.z, a1.w};
            float bb[4] = {bv.x, bv.y, bv.z, bv.w};
            #pragma unroll
            for (int i = 0; i < 8; i++)
                #pragma unroll
                for (int j = 0; j < 4; j++)
                    acc[i][j] += a[i] * bb[j];
        }
        __syncthreads();
    }
    #pragma unroll
    for (int i = 0; i < 8; i++) {
        float4 v = make_float4(acc[i][0], acc[i][1], acc[i][2], acc[i][3]);
        *(float4*)&C[(row0 + ty * 8 + i) * NCP + n0 + tx * 4] = v;
    }
}

// ---------------------------------------------------------------------------
struct MixAcc { float r00, r01, r10, r11, i00, i01, i10, i11; };

__device__ __forceinline__ void mix_zero(MixAcc& a) {
    a.r00 = a.r01 = a.r10 = a.r11 = 0.f;
    a.i00 = a.i01 = a.i10 = a.i11 = 0.f;
}

__device__ __forceinline__ void mix_pass(const float* __restrict__ sx,
                                         const float* __restrict__ sw,
                                         int b0, int k0, MixAcc& a) {
    #pragma unroll
    for (int j = 0; j < 32; j++) {
        float xr0 = sx[b0 * 64 + j],        xi0 = sx[b0 * 64 + 32 + j];
        float xr1 = sx[(b0 + 1) * 64 + j],  xi1 = sx[(b0 + 1) * 64 + 32 + j];
        float wr0 = sw[j * 32 + k0],        wr1 = sw[j * 32 + k0 + 1];
        float wi0 = sw[1024 + j * 32 + k0], wi1 = sw[1024 + j * 32 + k0 + 1];
        a.r00 += xr0 * wr0 - xi0 * wi0;  a.i00 += xr0 * wi0 + xi0 * wr0;
        a.r01 += xr0 * wr1 - xi0 * wi1;  a.i01 += xr0 * wi1 + xi0 * wr1;
        a.r10 += xr1 * wr0 - xi1 * wi0;  a.i10 += xr1 * wi0 + xi1 * wr0;
        a.r11 += xr1 * wr1 - xi1 * wi1;  a.i11 += xr1 * wi1 + xi1 * wr1;
    }
}

__device__ __forceinline__ void mix_store(float* __restrict__ dst, int m, int b0, int k0,
                                          const MixAcc& a, float invN) {
    float a0 = (k0 == 0 ? 1.f : 2.f) * invN;
    float a1 = 2.f * invN;
    int base0 = ((b0) * 512 + m) * 64 + k0;
    int base1 = ((b0 + 1) * 512 + m) * 64 + k0;
    dst[base0]      = a.r00 * a0;  dst[base0 + 1]  = a.r01 * a1;
    dst[base0 + 32] = a.i00 * a0;  dst[base0 + 33] = a.i01 * a1;
    dst[base1]      = a.r10 * a0;  dst[base1 + 1]  = a.r11 * a1;
    dst[base1 + 32] = a.i10 * a0;  dst[base1 + 33] = a.i11 * a1;
}

__global__ void mix_kernel() {
    __shared__ float sxf[4][2048];
    __shared__ float sW[2048];
    int m = blockIdx.x, tid = threadIdx.x;
    for (int s = 0; s < 4; s++)
        for (int i = tid; i < 2048; i += 256) {
            int b = i >> 6, c = i & 63;
            sxf[s][i] = g_xf[s][(b * 512 + m) * 64 + c];
        }
    int b0 = (tid >> 4) * 2;
    int k0 = (tid & 15) * 2;

    MixAcc a;
    mix_zero(a);
    __syncthreads();
    for (int i = tid; i < 2048; i += 256) sW[i] = g_W[0 * 512 * 2048 + m * 2048 + i];
    __syncthreads();
    mix_pass(sxf[1], sW, b0, k0, a);
    __syncthreads();
    for (int i = tid; i < 2048; i += 256) sW[i] = g_W[1 * 512 * 2048 + m * 2048 + i];
    __syncthreads();
    mix_pass(sxf[0], sW, b0, k0, a);
    mix_store(g_spec[0], m, b0, k0, a, 1.0f / 257.0f);

    mix_zero(a);
    __syncthreads();
    for (int i = tid; i < 2048; i += 256) sW[i] = g_W[2 * 512 * 2048 + m * 2048 + i];
    __syncthreads();
    mix_pass(sxf[0], sW, b0, k0, a);
    mix_store(g_spec[1], m, b0, k0, a, 1.0f / 257.0f);

    mix_zero(a);
    __syncthreads();
    for (int i = tid; i < 2048; i += 256) sW[i] = g_W[3 * 512 * 2048 + m * 2048 + i];
    __syncthreads();
    mix_pass(sxf[3], sW, b0, k0, a);
    __syncthreads();
    for (int i = tid; i < 2048; i += 256) sW[i] = g_W[4 * 512 * 2048 + m * 2048 + i];
    __syncthreads();
    mix_pass(sxf[2], sW, b0, k0, a);
    mix_store(g_spec[2], m, b0, k0, a, 1.0f / 130.0f);

    mix_zero(a);
    __syncthreads();
    for (int i = tid; i < 2048; i += 256) sW[i] = g_W[5 * 512 * 2048 + m * 2048 + i];
    __syncthreads();
    mix_pass(sxf[2], sW, b0, k0, a);
    mix_store(g_spec[3], m, b0, k0, a, 1.0f / 130.0f);
}

// ---------------------------------------------------------------------------
// Fused idwt level1 + level0 + output transpose. Block = (32 m's, one b).
// Dynamic smem: yb[258][33], rlo[257][33], rhi[257][33].
__global__ __launch_bounds__(256) void idwt_fused(float* __restrict__ out) {
    extern __shared__ float dyn[];
    float* yb  = dyn;                    // 258*33
    float* rlo = dyn + 258 * 33;         // 257*33
    float* rhi = rlo + 257 * 33;         // 257*33
    int m0 = blockIdx.x * 32, b = blockIdx.y;
    int tid = threadIdx.x, lane = tid & 31, wid = tid >> 5;

    for (int c = wid; c < 32; c += 8) {
        int row = b * 512 + m0 + c;
        for (int t = lane; t < 130; t += 32) {
            rlo[t * 33 + c] = g_s2[row * N2PI + t];
            rhi[t * 33 + c] = g_ud1[row * N2PI + t];
        }
    }
    __syncthreads();
    for (int i = tid; i < 258 * 32; i += 256) {
        int n = i >> 5, c = i & 31;
        float v;
        if (n & 1) {
            int i0 = (n - 1) >> 1, i1 = (n + 1) >> 1;
            v = rlo[i0 * 33 + c] * G3 + rhi[i0 * 33 + c] * H3
              + rlo[i1 * 33 + c] * G1 + rhi[i1 * 33 + c] * H1;
        } else {
            int i0 = n >> 1, i1 = i0 + 1;
            v = rlo[i0 * 33 + c] * G2 + rhi[i0 * 33 + c] * H2
              + rlo[i1 * 33 + c] * G0 + rhi[i1 * 33 + c] * H0;
        }
        yb[n * 33 + c] = v;
    }
    __syncthreads();
    for (int c = wid; c < 32; c += 8) {
        int row = b * 512 + m0 + c;
        for (int t = lane; t < 257; t += 32) {
            rlo[t * 33 + c] = yb[t * 33 + c] + g_us1[row * N1PI + t];
            rhi[t * 33 + c] = g_ud0[row * N1PI + t];
        }
    }
    __syncthreads();
    for (int i = tid; i < 512 * 32; i += 256) {
        int n = i >> 5, c = i & 31;
        float v;
        if (n & 1) {
            int i0 = (n - 1) >> 1, i1 = (n + 1) >> 1;
            v = rlo[i0 * 33 + c] * G3 + rhi[i0 * 33 + c] * H3
              + rlo[i1 * 33 + c] * G1 + rhi[i1 * 33 + c] * H1;
        } else {
            int i0 = n >> 1, i1 = i0 + 1;
            v = rlo[i0 * 33 + c] * G2 + rhi[i0 * 33 + c] * H2
              + rlo[i1 * 33 + c] * G0 + rhi[i1 * 33 + c] * H0;
        }
        out[(b * 512 + n) * 512 + m0 + c] = v;
    }
}

// ---------------------------------------------------------------------------
extern "C" void kernel_launch(void* const* d_in, const int* in_sizes, int n_in,
                              void* d_out, int out_size) {
    (void)in_sizes; (void)n_in; (void)out_size;
    const float* x = (const float*)d_in[0];

    const int dwt_smem  = (512 * 33 + 257 * 33) * 4;
    const int idwt_smem = (258 * 33 + 2 * 257 * 33) * 4;
    cudaFuncSetAttribute(dwt_fused,  cudaFuncAttributeMaxDynamicSharedMemorySize, dwt_smem);
    cudaFuncSetAttribute(idwt_fused, cudaFuncAttributeMaxDynamicSharedMemorySize, idwt_smem);

    prep_basis<<<(N1 * 64 + N2 * 64 + 255) / 256, 256>>>();
    pack_weights<<<2048, 256>>>(
        (const float*)d_in[1],  (const float*)d_in[2],
        (const float*)d_in[3],  (const float*)d_in[4],
        (const float*)d_in[5],  (const float*)d_in[6],
        (const float*)d_in[7],  (const float*)d_in[8],
        (const float*)d_in[9],  (const float*)d_in[10],
        (const float*)d_in[11], (const float*)d_in[12],
        (const float*)d_in[13], (const float*)d_in[14]);

    dwt_fused<<<dim3(16, 32), 256, dwt_smem>>>(x);
    fwd_gemm<<<dim3(1, 128, 4), 256>>>();
    mix_kernel<<<512, 256>>>();
    inv_gemm<<<dim3(8, 128, 2), 256>>>();
    idwt_fused<<<dim3(16, 32), 256, idwt_smem>>>((float*)d_out);
}

// round 4
// speedup vs baseline: 1.3105x; 1.0980x over previous
#include <cuda_runtime.h>
#include <math.h>

// ---------------------------------------------------------------------------
// WaveletF1DModule: 2-level sym2 DWT + truncated-DFT spectral conv (32 modes).
// B=32, N=512, M=512. row = b*512 + m. Signal lens: 257 (L0), 130 (L1).
// DFT GEMMs run on tensor cores: tf32 mma.sync with 2-term split (3xTF32).
// ---------------------------------------------------------------------------

#define RTOT 16384
#define N1 257
#define N2 130
#define N1PF 288   // fwd stride (lo1/hi1), 9 k-tiles of 32
#define N2PF 160   // fwd stride (lo2/hi2), 5 k-tiles
#define N1PI 320   // inv out stride (ud0/us1), 5 n-tiles of 64
#define N2PI 192   // inv out stride (ud1/s2), 3 n-tiles

__device__ float g_lo1[RTOT * N1PF];
__device__ float g_hi1[RTOT * N1PF];
__device__ float g_lo2[RTOT * N2PF];
__device__ float g_hi2[RTOT * N2PF];
__device__ float g_xf[4][RTOT * 64];     // 0=lo1,1=hi1,2=lo2,3=hi2 (re[32]|im[32])
__device__ float g_spec[4][RTOT * 64];   // 0=Ud0,1=Us1,2=Ud1,3=S2 (a_k-scaled)
__device__ float g_ud0[RTOT * N1PI];
__device__ float g_us1[RTOT * N1PI];
__device__ float g_ud1[RTOT * N2PI];
__device__ float g_s2 [RTOT * N2PI];
// tf32-split DFT bases (hi = rna-tf32, lo = residual). Pad regions stay zero.
__device__ float g_Bf257h[N1PF * 64], g_Bf257l[N1PF * 64];
__device__ float g_Bi257h[64 * N1PI], g_Bi257l[64 * N1PI];
__device__ float g_Bf130h[N2PF * 64], g_Bf130l[N2PF * 64];
__device__ float g_Bi130h[64 * N2PI], g_Bi130l[64 * N2PI];
__device__ float g_W[6 * 512 * 2048];    // [w][m][ri*1024 + j*32 + k]

#define G0 0.48296291314469025f
#define G1 0.836516303737469f
#define G2 0.22414386804185735f
#define G3 (-0.12940952255092145f)
#define H0 (-0.12940952255092145f)
#define H1 (-0.22414386804185735f)
#define H2 0.836516303737469f
#define H3 (-0.48296291314469025f)

__device__ __forceinline__ unsigned tf32_hi_bits(float v) {
    unsigned r;
    asm("cvt.rna.tf32.f32 %0, %1;" : "=r"(r) : "f"(v));
    return r;
}

__device__ __forceinline__ void mma_tf32(float c[4], const unsigned a[4], const unsigned b[2]) {
    asm volatile(
        "mma.sync.aligned.m16n8k8.row.col.f32.tf32.tf32.f32 "
        "{%0,%1,%2,%3}, {%4,%5,%6,%7}, {%8,%9}, {%0,%1,%2,%3};\n"
        : "+f"(c[0]), "+f"(c[1]), "+f"(c[2]), "+f"(c[3])
        : "r"(a[0]), "r"(a[1]), "r"(a[2]), "r"(a[3]), "r"(b[0]), "r"(b[1]));
}

// ---------------------------------------------------------------------------
__global__ void prep_basis() {
    int idx = blockIdx.x * blockDim.x + threadIdx.x;
    const double TWO_PI = 6.283185307179586476925286766559;
    if (idx < N1 * 64) {
        int t = idx / 64, c = idx % 64, k = c & 31;
        double th = TWO_PI * (double)(k * t) / 257.0;
        float v = (c < 32) ? (float)cos(th) : (float)(-sin(th));
        float h = __uint_as_float(tf32_hi_bits(v));
        g_Bf257h[t * 64 + c] = h;      g_Bf257l[t * 64 + c] = v - h;
        g_Bi257h[c * N1PI + t] = h;    g_Bi257l[c * N1PI + t] = v - h;
    }
    int idx2 = idx - N1 * 64;
    if (idx2 >= 0 && idx2 < N2 * 64) {
        int t = idx2 / 64, c = idx2 % 64, k = c & 31;
        double th = TWO_PI * (double)(k * t) / 130.0;
        float v = (c < 32) ? (float)cos(th) : (float)(-sin(th));
        float h = __uint_as_float(tf32_hi_bits(v));
        g_Bf130h[t * 64 + c] = h;      g_Bf130l[t * 64 + c] = v - h;
        g_Bi130h[c * N2PI + t] = h;    g_Bi130l[c * N2PI + t] = v - h;
    }
}

// ---------------------------------------------------------------------------
// Weight halves: level0 (512,86,86), level1 (512,65,65), D (512,132,132).
__global__ void pack_weights(const float* __restrict__ l0k0_r, const float* __restrict__ l0k0_i,
                             const float* __restrict__ l0k1_r, const float* __restrict__ l0k1_i,
                             const float* __restrict__ l0k2_r, const float* __restrict__ l0k2_i,
                             const float* __restrict__ l1k0_r, const float* __restrict__ l1k0_i,
                             const float* __restrict__ l1k1_r, const float* __restrict__ l1k1_i,
                             const float* __restrict__ l1k2_r, const float* __restrict__ l1k2_i,
                             const float* __restrict__ D_r,    const float* __restrict__ D_i) {
    int idx = blockIdx.x * blockDim.x + threadIdx.x;
    if (idx >= 512 * 1024) return;
    int m = idx >> 10, j = (idx >> 5) & 31, k = idx & 31;
    int dst = m * 2048 + j * 32 + k;
    int s86  = (m * 86 + j) * 86 + k;
    int s65  = (m * 65 + j) * 65 + k;
    int s132 = (m * 132 + j) * 132 + k;
    g_W[0 * 512 * 2048 + dst]        = l0k0_r[s86];
    g_W[0 * 512 * 2048 + dst + 1024] = l0k0_i[s86];
    g_W[1 * 512 * 2048 + dst]        = l0k1_r[s86];
    g_W[1 * 512 * 2048 + dst + 1024] = l0k1_i[s86];
    g_W[2 * 512 * 2048 + dst]        = l0k2_r[s86];
    g_W[2 * 512 * 2048 + dst + 1024] = l0k2_i[s86];
    g_W[3 * 512 * 2048 + dst]        = l1k0_r[s65];
    g_W[3 * 512 * 2048 + dst + 1024] = l1k0_i[s65];
    g_W[4 * 512 * 2048 + dst]        = l1k1_r[s65];
    g_W[4 * 512 * 2048 + dst + 1024] = l1k1_i[s65];
    g_W[5 * 512 * 2048 + dst]        = l1k2_r[s65] + D_r[s132];
    g_W[5 * 512 * 2048 + dst + 1024] = l1k2_i[s65] + D_i[s132];
}

// ---------------------------------------------------------------------------
// Fused dwt level0 + level1.
__global__ __launch_bounds__(256) void dwt_fused(const float* __restrict__ x) {
    extern __shared__ float dyn[];
    float* sx = dyn;                // 512*33
    float* sb = dyn + 512 * 33;     // 257*33
    int m0 = blockIdx.x * 32, b = blockIdx.y;
    int tid = threadIdx.x, lane = tid & 31, wid = tid >> 5;

    for (int i = tid; i < 512 * 32; i += 256) {
        int n = i >> 5, c = i & 31;
        sx[n * 33 + c] = x[(b * 512 + n) * 512 + m0 + c];
    }
    __syncthreads();
    for (int i = tid; i < 257 * 32; i += 256) {
        int t = i >> 5, c = i & 31, n = 2 * t - 2;
        float v[4];
        #pragma unroll
        for (int k = 0; k < 4; k++) {
            int nn = n + k; nn = nn < 0 ? -nn : (nn > 511 ? 1022 - nn : nn);
            v[k] = sx[nn * 33 + c];
        }
        sb[t * 33 + c] = H0 * v[0] + H1 * v[1] + H2 * v[2] + H3 * v[3];
    }
    __syncthreads();
    for (int c = wid; c < 32; c += 8) {
        int row = b * 512 + m0 + c;
        for (int t = lane; t < 257; t += 32) g_hi1[row * N1PF + t] = sb[t * 33 + c];
    }
    __syncthreads();
    for (int i = tid; i < 257 * 32; i += 256) {
        int t = i >> 5, c = i & 31, n = 2 * t - 2;
        float v[4];
        #pragma unroll
        for (int k = 0; k < 4; k++) {
            int nn = n + k; nn = nn < 0 ? -nn : (nn > 511 ? 1022 - nn : nn);
            v[k] = sx[nn * 33 + c];
        }
        sb[t * 33 + c] = G0 * v[0] + G1 * v[1] + G2 * v[2] + G3 * v[3];
    }
    __syncthreads();
    float* s2lo = sx;
    float* s2hi = sx + 130 * 33;
    for (int c = wid; c < 32; c += 8) {
        int row = b * 512 + m0 + c;
        for (int t = lane; t < 257; t += 32) g_lo1[row * N1PF + t] = sb[t * 33 + c];
    }
    for (int i = tid; i < 130 * 32; i += 256) {
        int t = i >> 5, c = i & 31, n = 2 * t - 2;
        float v[4];
        #pragma unroll
        for (int k = 0; k < 4; k++) {
            int nn = n + k; nn = nn < 0 ? -nn : (nn > 256 ? 512 - nn : nn);
            v[k] = sb[nn * 33 + c];
        }
        s2lo[t * 33 + c] = G0 * v[0] + G1 * v[1] + G2 * v[2] + G3 * v[3];
        s2hi[t * 33 + c] = H0 * v[0] + H1 * v[1] + H2 * v[2] + H3 * v[3];
    }
    __syncthreads();
    for (int c = wid; c < 32; c += 8) {
        int row = b * 512 + m0 + c;
        for (int t = lane; t < 130; t += 32) {
            g_lo2[row * N2PF + t] = s2lo[t * 33 + c];
            g_hi2[row * N2PF + t] = s2hi[t * 33 + c];
        }
    }
}

// ---------------------------------------------------------------------------
// tf32 split GEMM core: C[row0..+128][n0..+64] = A[128 x 32*kit] @ B[.][64]
// A split to hi/lo on smem store; B pre-split (Bh/Bl).
__device__ __forceinline__ void gemm_tf32_core(
    const float* __restrict__ A, int lda, int kit,
    const float* __restrict__ Bh, const float* __restrict__ Bl, int ldb, int bn0,
    float* __restrict__ C, int ldc, int cn0, int row0)
{
    extern __shared__ float smem[];
    float* Ah  = smem;                 // 128*36
    float* Al  = Ah + 128 * 36;
    float* Bsh = Al + 128 * 36;        // 32*72
    float* Bsl = Bsh + 32 * 72;

    int tid = threadIdx.x, lane = tid & 31, wid = tid >> 5;
    int wm = wid >> 1, wn = wid & 1;
    int gr = lane >> 2, tg = lane & 3;

    float acc[2][4][4] = {};

    for (int kt = 0; kt < kit; kt++) {
        int k0 = kt * 32;
        #pragma unroll
        for (int it = 0; it < 4; it++) {
            int lin = it * 256 + tid;
            int r = lin >> 3, kq = (lin & 7) * 4;
            float4 v = *(const float4*)&A[(row0 + r) * lda + k0 + kq];
            float hx = __uint_as_float(tf32_hi_bits(v.x));
            float hy = __uint_as_float(tf32_hi_bits(v.y));
            float hz = __uint_as_float(tf32_hi_bits(v.z));
            float hw = __uint_as_float(tf32_hi_bits(v.w));
            *(float4*)&Ah[r * 36 + kq] = make_float4(hx, hy, hz, hw);
            *(float4*)&Al[r * 36 + kq] = make_float4(v.x - hx, v.y - hy, v.z - hz, v.w - hw);
        }
        #pragma unroll
        for (int it = 0; it < 2; it++) {
            int lin = it * 256 + tid;
            int kb = lin >> 4, cq = (lin & 15) * 4;
            *(float4*)&Bsh[kb * 72 + cq] = *(const float4*)&Bh[(k0 + kb) * ldb + bn0 + cq];
            *(float4*)&Bsl[kb * 72 + cq] = *(const float4*)&Bl[(k0 + kb) * ldb + bn0 + cq];
        }
        __syncthreads();
        #pragma unroll
        for (int k8 = 0; k8 < 32; k8 += 8) {
            unsigned ah[2][4], al[2][4], bh[4][2], bl[4][2];
            #pragma unroll
            for (int mt = 0; mt < 2; mt++) {
                int rb = wm * 32 + mt * 16;
                ah[mt][0] = __float_as_uint(Ah[(rb + gr) * 36 + k8 + tg]);
                ah[mt][1] = __float_as_uint(Ah[(rb + gr + 8) * 36 + k8 + tg]);
                ah[mt][2] = __float_as_uint(Ah[(rb + gr) * 36 + k8 + tg + 4]);
                ah[mt][3] = __float_as_uint(Ah[(rb + gr + 8) * 36 + k8 + tg + 4]);
                al[mt][0] = __float_as_uint(Al[(rb + gr) * 36 + k8 + tg]);
                al[mt][1] = __float_as_uint(Al[(rb + gr + 8) * 36 + k8 + tg]);
                al[mt][2] = __float_as_uint(Al[(rb + gr) * 36 + k8 + tg + 4]);
                al[mt][3] = __float_as_uint(Al[(rb + gr + 8) * 36 + k8 + tg + 4]);
            }
            #pragma unroll
            for (int nt = 0; nt < 4; nt++) {
                int nb = wn * 32 + nt * 8 + gr;
                bh[nt][0] = __float_as_uint(Bsh[(k8 + tg) * 72 + nb]);
                bh[nt][1] = __float_as_uint(Bsh[(k8 + tg + 4) * 72 + nb]);
                bl[nt][0] = __float_as_uint(Bsl[(k8 + tg) * 72 + nb]);
                bl[nt][1] = __float_as_uint(Bsl[(k8 + tg + 4) * 72 + nb]);
            }
            #pragma unroll
            for (int mt = 0; mt < 2; mt++)
                #pragma unroll
                for (int nt = 0; nt < 4; nt++) {
                    mma_tf32(acc[mt][nt], ah[mt], bh[nt]);
                    mma_tf32(acc[mt][nt], ah[mt], bl[nt]);
                    mma_tf32(acc[mt][nt], al[mt], bh[nt]);
                }
        }
        __syncthreads();
    }
    #pragma unroll
    for (int mt = 0; mt < 2; mt++)
        #pragma unroll
        for (int nt = 0; nt < 4; nt++) {
            int r = row0 + wm * 32 + mt * 16 + gr;
            int cc = cn0 + wn * 32 + nt * 8 + tg * 2;
            *(float2*)&C[r * ldc + cc]       = make_float2(acc[mt][nt][0], acc[mt][nt][1]);
            *(float2*)&C[(r + 8) * ldc + cc] = make_float2(acc[mt][nt][2], acc[mt][nt][3]);
        }
}

// Forward DFT: z = 0..3 -> lo1,hi1,lo2,hi2
__global__ __launch_bounds__(256) void fwd_gemm_tf32() {
    int z = blockIdx.z, row0 = blockIdx.y * 128;
    if (z == 0)      gemm_tf32_core(g_lo1, N1PF, 9, g_Bf257h, g_Bf257l, 64, 0, &g_xf[0][0], 64, 0, row0);
    else if (z == 1) gemm_tf32_core(g_hi1, N1PF, 9, g_Bf257h, g_Bf257l, 64, 0, &g_xf[1][0], 64, 0, row0);
    else if (z == 2) gemm_tf32_core(g_lo2, N2PF, 5, g_Bf130h, g_Bf130l, 64, 0, &g_xf[2][0], 64, 0, row0);
    else             gemm_tf32_core(g_hi2, N2PF, 5, g_Bf130h, g_Bf130l, 64, 0, &g_xf[3][0], 64, 0, row0);
}

// Inverse DFT: x < 5 -> Bi257 n-tiles (z: spec0->ud0, spec1->us1);
//              x >= 5 -> Bi130 n-tiles (z: spec2->ud1, spec3->s2)
__global__ __launch_bounds__(256) void inv_gemm_tf32() {
    int xb = blockIdx.x, z = blockIdx.z, row0 = blockIdx.y * 128;
    if (xb < 5) {
        int n0 = xb * 64;
        if (z == 0) gemm_tf32_core(&g_spec[0][0], 64, 2, g_Bi257h, g_Bi257l, N1PI, n0, g_ud0, N1PI, n0, row0);
        else        gemm_tf32_core(&g_spec[1][0], 64, 2, g_Bi257h, g_Bi257l, N1PI, n0, g_us1, N1PI, n0, row0);
    } else {
        int n0 = (xb - 5) * 64;
        if (z == 0) gemm_tf32_core(&g_spec[2][0], 64, 2, g_Bi130h, g_Bi130l, N2PI, n0, g_ud1, N2PI, n0, row0);
        else        gemm_tf32_core(&g_spec[3][0], 64, 2, g_Bi130h, g_Bi130l, N2PI, n0, g_s2,  N2PI, n0, row0);
    }
}

// ---------------------------------------------------------------------------
struct MixAcc { float r00, r01, r10, r11, i00, i01, i10, i11; };

__device__ __forceinline__ void mix_zero(MixAcc& a) {
    a.r00 = a.r01 = a.r10 = a.r11 = 0.f;
    a.i00 = a.i01 = a.i10 = a.i11 = 0.f;
}

__device__ __forceinline__ void mix_pass(const float* __restrict__ sx,
                                         const float* __restrict__ sw,
                                         int b0, int k0, MixAcc& a) {
    #pragma unroll
    for (int j = 0; j < 32; j++) {
        float xr0 = sx[b0 * 64 + j],        xi0 = sx[b0 * 64 + 32 + j];
        float xr1 = sx[(b0 + 1) * 64 + j],  xi1 = sx[(b0 + 1) * 64 + 32 + j];
        float wr0 = sw[j * 32 + k0],        wr1 = sw[j * 32 + k0 + 1];
        float wi0 = sw[1024 + j * 32 + k0], wi1 = sw[1024 + j * 32 + k0 + 1];
        a.r00 += xr0 * wr0 - xi0 * wi0;  a.i00 += xr0 * wi0 + xi0 * wr0;
        a.r01 += xr0 * wr1 - xi0 * wi1;  a.i01 += xr0 * wi1 + xi0 * wr1;
        a.r10 += xr1 * wr0 - xi1 * wi0;  a.i10 += xr1 * wi0 + xi1 * wr0;
        a.r11 += xr1 * wr1 - xi1 * wi1;  a.i11 += xr1 * wi1 + xi1 * wr1;
    }
}

__device__ __forceinline__ void mix_store(float* __restrict__ dst, int m, int b0, int k0,
                                          const MixAcc& a, float invN) {
    float a0 = (k0 == 0 ? 1.f : 2.f) * invN;
    float a1 = 2.f * invN;
    int base0 = ((b0) * 512 + m) * 64 + k0;
    int base1 = ((b0 + 1) * 512 + m) * 64 + k0;
    dst[base0]      = a.r00 * a0;  dst[base0 + 1]  = a.r01 * a1;
    dst[base0 + 32] = a.i00 * a0;  dst[base0 + 33] = a.i01 * a1;
    dst[base1]      = a.r10 * a0;  dst[base1 + 1]  = a.r11 * a1;
    dst[base1 + 32] = a.i10 * a0;  dst[base1 + 33] = a.i11 * a1;
}

__global__ void mix_kernel() {
    __shared__ float sxf[4][2048];
    __shared__ float sW[2048];
    int m = blockIdx.x, tid = threadIdx.x;
    for (int s = 0; s < 4; s++)
        for (int i = tid; i < 2048; i += 256) {
            int b = i >> 6, c = i & 63;
            sxf[s][i] = g_xf[s][(b * 512 + m) * 64 + c];
        }
    int b0 = (tid >> 4) * 2;
    int k0 = (tid & 15) * 2;

    MixAcc a;
    mix_zero(a);
    __syncthreads();
    for (int i = tid; i < 2048; i += 256) sW[i] = g_W[0 * 512 * 2048 + m * 2048 + i];
    __syncthreads();
    mix_pass(sxf[1], sW, b0, k0, a);
    __syncthreads();
    for (int i = tid; i < 2048; i += 256) sW[i] = g_W[1 * 512 * 2048 + m * 2048 + i];
    __syncthreads();
    mix_pass(sxf[0], sW, b0, k0, a);
    mix_store(g_spec[0], m, b0, k0, a, 1.0f / 257.0f);

    mix_zero(a);
    __syncthreads();
    for (int i = tid; i < 2048; i += 256) sW[i] = g_W[2 * 512 * 2048 + m * 2048 + i];
    __syncthreads();
    mix_pass(sxf[0], sW, b0, k0, a);
    mix_store(g_spec[1], m, b0, k0, a, 1.0f / 257.0f);

    mix_zero(a);
    __syncthreads();
    for (int i = tid; i < 2048; i += 256) sW[i] = g_W[3 * 512 * 2048 + m * 2048 + i];
    __syncthreads();
    mix_pass(sxf[3], sW, b0, k0, a);
    __syncthreads();
    for (int i = tid; i < 2048; i += 256) sW[i] = g_W[4 * 512 * 2048 + m * 2048 + i];
    __syncthreads();
    mix_pass(sxf[2], sW, b0, k0, a);
    mix_store(g_spec[2], m, b0, k0, a, 1.0f / 130.0f);

    mix_zero(a);
    __syncthreads();
    for (int i = tid; i < 2048; i += 256) sW[i] = g_W[5 * 512 * 2048 + m * 2048 + i];
    __syncthreads();
    mix_pass(sxf[2], sW, b0, k0, a);
    mix_store(g_spec[3], m, b0, k0, a, 1.0f / 130.0f);
}

// ---------------------------------------------------------------------------
// Fused idwt level1 + level0 + output transpose.
__global__ __launch_bounds__(256) void idwt_fused(float* __restrict__ out) {
    extern __shared__ float dyn[];
    float* yb  = dyn;                    // 258*33
    float* rlo = dyn + 258 * 33;         // 257*33
    float* rhi = rlo + 257 * 33;         // 257*33
    int m0 = blockIdx.x * 32, b = blockIdx.y;
    int tid = threadIdx.x, lane = tid & 31, wid = tid >> 5;

    for (int c = wid; c < 32; c += 8) {
        int row = b * 512 + m0 + c;
        for (int t = lane; t < 130; t += 32) {
            rlo[t * 33 + c] = g_s2[row * N2PI + t];
            rhi[t * 33 + c] = g_ud1[row * N2PI + t];
        }
    }
    __syncthreads();
    for (int i = tid; i < 258 * 32; i += 256) {
        int n = i >> 5, c = i & 31;
        float v;
        if (n & 1) {
            int i0 = (n - 1) >> 1, i1 = (n + 1) >> 1;
            v = rlo[i0 * 33 + c] * G3 + rhi[i0 * 33 + c] * H3
              + rlo[i1 * 33 + c] * G1 + rhi[i1 * 33 + c] * H1;
        } else {
            int i0 = n >> 1, i1 = i0 + 1;
            v = rlo[i0 * 33 + c] * G2 + rhi[i0 * 33 + c] * H2
              + rlo[i1 * 33 + c] * G0 + rhi[i1 * 33 + c] * H0;
        }
        yb[n * 33 + c] = v;
    }
    __syncthreads();
    for (int c = wid; c < 32; c += 8) {
        int row = b * 512 + m0 + c;
        for (int t = lane; t < 257; t += 32) {
            rlo[t * 33 + c] = yb[t * 33 + c] + g_us1[row * N1PI + t];
            rhi[t * 33 + c] = g_ud0[row * N1PI + t];
        }
    }
    __syncthreads();
    for (int i = tid; i < 512 * 32; i += 256) {
        int n = i >> 5, c = i & 31;
        float v;
        if (n & 1) {
            int i0 = (n - 1) >> 1, i1 = (n + 1) >> 1;
            v = rlo[i0 * 33 + c] * G3 + rhi[i0 * 33 + c] * H3
              + rlo[i1 * 33 + c] * G1 + rhi[i1 * 33 + c] * H1;
        } else {
            int i0 = n >> 1, i1 = i0 + 1;
            v = rlo[i0 * 33 + c] * G2 + rhi[i0 * 33 + c] * H2
              + rlo[i1 * 33 + c] * G0 + rhi[i1 * 33 + c] * H0;
        }
        out[(b * 512 + n) * 512 + m0 + c] = v;
    }
}

// ---------------------------------------------------------------------------
extern "C" void kernel_launch(void* const* d_in, const int* in_sizes, int n_in,
                              void* d_out, int out_size) {
    (void)in_sizes; (void)n_in; (void)out_size;
    const float* x = (const float*)d_in[0];

    const int dwt_smem  = (512 * 33 + 257 * 33) * 4;
    const int idwt_smem = (258 * 33 + 2 * 257 * 33) * 4;
    const int gemm_smem = (2 * 128 * 36 + 2 * 32 * 72) * 4;   // 55296 B
    cudaFuncSetAttribute(dwt_fused,     cudaFuncAttributeMaxDynamicSharedMemorySize, dwt_smem);
    cudaFuncSetAttribute(idwt_fused,    cudaFuncAttributeMaxDynamicSharedMemorySize, idwt_smem);
    cudaFuncSetAttribute(fwd_gemm_tf32, cudaFuncAttributeMaxDynamicSharedMemorySize, gemm_smem);
    cudaFuncSetAttribute(inv_gemm_tf32, cudaFuncAttributeMaxDynamicSharedMemorySize, gemm_smem);

    prep_basis<<<(N1 * 64 + N2 * 64 + 255) / 256, 256>>>();
    pack_weights<<<2048, 256>>>(
        (const float*)d_in[1],  (const float*)d_in[2],
        (const float*)d_in[3],  (const float*)d_in[4],
        (const float*)d_in[5],  (const float*)d_in[6],
        (const float*)d_in[7],  (const float*)d_in[8],
        (const float*)d_in[9],  (const float*)d_in[10],
        (const float*)d_in[11], (const float*)d_in[12],
        (const float*)d_in[13], (const float*)d_in[14]);

    dwt_fused<<<dim3(16, 32), 256, dwt_smem>>>(x);
    fwd_gemm_tf32<<<dim3(1, 128, 4), 256, gemm_smem>>>();
    mix_kernel<<<512, 256>>>();
    inv_gemm_tf32<<<dim3(8, 128, 2), 256, gemm_smem>>>();
    idwt_fused<<<dim3(16, 32), 256, idwt_smem>>>((float*)d_out);
}